// round 2
// baseline (speedup 1.0000x reference)
#include <cuda_runtime.h>
#include <math.h>

#define BATCH    4096
#define N_FEAT   256
#define HIDDEN   128
#define NTASK    1000
#define W1_ELEMS (N_FEAT * HIDDEN)   // 32768
#define SMAX     8                   // samples processed per W1 pass

// Scratch (allocation-free: __device__ globals)
__device__ int g_count[NTASK];
__device__ int g_cursor[NTASK];
__device__ int g_offset[NTASK + 1];
__device__ int g_sorted[BATCH];

__global__ void zero_kernel() {
    int i = blockIdx.x * blockDim.x + threadIdx.x;
    if (i < NTASK) { g_count[i] = 0; g_cursor[i] = 0; }
}

__global__ void hist_kernel(const int* __restrict__ task_ids) {
    int i = blockIdx.x * blockDim.x + threadIdx.x;
    if (i < BATCH) atomicAdd(&g_count[task_ids[i]], 1);
}

// Single-block inclusive Hillis-Steele scan over 1024 slots (1000 used).
__global__ void scan_kernel() {
    __shared__ int s[1024];
    const int tid = threadIdx.x;
    const int v0 = (tid < NTASK) ? g_count[tid] : 0;
    s[tid] = v0;
    for (int off = 1; off < 1024; off <<= 1) {
        __syncthreads();
        const int v = (tid >= off) ? s[tid - off] : 0;
        __syncthreads();
        s[tid] += v;
    }
    if (tid < NTASK) g_offset[tid] = s[tid] - v0;      // exclusive
    if (tid == NTASK - 1) g_offset[NTASK] = s[tid];    // total = BATCH
}

__global__ void scatter_kernel(const int* __restrict__ task_ids) {
    int i = blockIdx.x * blockDim.x + threadIdx.x;
    if (i < BATCH) {
        const int t = task_ids[i];
        const int pos = g_offset[t] + atomicAdd(&g_cursor[t], 1);
        g_sorted[pos] = i;
    }
}

// One block per task; 128 threads (4 warps). Warp w handles f in [64w,64w+64);
// lane owns 4 hidden cols via float4. Up to SMAX samples share one W1 read.
__global__ __launch_bounds__(128) void task_mlp_grouped(
    const float* __restrict__ x,        // [B, 256]
    const float* __restrict__ l1_emb,   // [T, 256*128]
    const float* __restrict__ l1_bias,  // [T, 128]
    const float* __restrict__ l2_emb,   // [T, 128]
    const float* __restrict__ l2_bias,  // [T, 1]
    float*       __restrict__ out)      // [B, 1]
{
    const int t    = blockIdx.x;
    const int base = g_offset[t];
    const int n    = g_offset[t + 1] - base;
    if (n == 0) return;

    const int tid  = threadIdx.x;
    const int warp = tid >> 5;
    const int lane = tid & 31;

    __shared__ float xs[SMAX][N_FEAT];            // 8 KB
    __shared__ float partial[4][SMAX][HIDDEN];    // 16 KB
    __shared__ float red[4][SMAX];
    __shared__ int   sidx[SMAX];

    const float4* __restrict__ w1v = (const float4*)(l1_emb + (long)t * W1_ELEMS);
    const float b1v = l1_bias[t * HIDDEN + tid];
    const float w2v = l2_emb[t * HIDDEN + tid];
    const float b2  = l2_bias[t];

    for (int c0 = 0; c0 < n; c0 += SMAX) {
        const int nc = min(SMAX, n - c0);

        if (tid < SMAX) sidx[tid] = (tid < nc) ? g_sorted[base + c0 + tid] : 0;
        __syncthreads();

        // Stage x rows into smem, zero-padded past nc
        for (int i = tid; i < SMAX * (N_FEAT / 4); i += 128) {
            const int s = i >> 6, col = i & 63;
            float4 v = make_float4(0.f, 0.f, 0.f, 0.f);
            if (s < nc)
                v = ((const float4*)(x + (long)sidx[s] * N_FEAT))[col];
            ((float4*)xs[s])[col] = v;
        }
        __syncthreads();

        float4 acc[SMAX];
        #pragma unroll
        for (int s = 0; s < SMAX; ++s) acc[s] = make_float4(0.f, 0.f, 0.f, 0.f);

        const int f0 = warp * 64;
        #pragma unroll 2
        for (int fq = 0; fq < 16; ++fq) {           // 4 f's per iteration
            const int f = f0 + fq * 4;
            const float4 wv0 = w1v[(f + 0) * (HIDDEN / 4) + lane];
            const float4 wv1 = w1v[(f + 1) * (HIDDEN / 4) + lane];
            const float4 wv2 = w1v[(f + 2) * (HIDDEN / 4) + lane];
            const float4 wv3 = w1v[(f + 3) * (HIDDEN / 4) + lane];
            #pragma unroll
            for (int s = 0; s < SMAX; ++s) {
                const float4 xv = ((const float4*)xs[s])[f >> 2];
                acc[s].x = fmaf(xv.x, wv0.x, acc[s].x);
                acc[s].y = fmaf(xv.x, wv0.y, acc[s].y);
                acc[s].z = fmaf(xv.x, wv0.z, acc[s].z);
                acc[s].w = fmaf(xv.x, wv0.w, acc[s].w);
                acc[s].x = fmaf(xv.y, wv1.x, acc[s].x);
                acc[s].y = fmaf(xv.y, wv1.y, acc[s].y);
                acc[s].z = fmaf(xv.y, wv1.z, acc[s].z);
                acc[s].w = fmaf(xv.y, wv1.w, acc[s].w);
                acc[s].x = fmaf(xv.z, wv2.x, acc[s].x);
                acc[s].y = fmaf(xv.z, wv2.y, acc[s].y);
                acc[s].z = fmaf(xv.z, wv2.z, acc[s].z);
                acc[s].w = fmaf(xv.z, wv2.w, acc[s].w);
                acc[s].x = fmaf(xv.w, wv3.x, acc[s].x);
                acc[s].y = fmaf(xv.w, wv3.y, acc[s].y);
                acc[s].z = fmaf(xv.w, wv3.z, acc[s].z);
                acc[s].w = fmaf(xv.w, wv3.w, acc[s].w);
            }
        }
        #pragma unroll
        for (int s = 0; s < SMAX; ++s)
            ((float4*)partial[warp][s])[lane] = acc[s];
        __syncthreads();

        // Epilogue: thread tid == hidden col
        #pragma unroll
        for (int s = 0; s < SMAX; ++s) {
            float h = partial[0][s][tid] + partial[1][s][tid]
                    + partial[2][s][tid] + partial[3][s][tid] + b1v;
            h = 0.5f * h * (1.0f + erff(h * 0.70710678118654752f));  // exact GELU
            float v = h * w2v;
            #pragma unroll
            for (int o = 16; o > 0; o >>= 1)
                v += __shfl_down_sync(0xffffffffu, v, o);
            if (lane == 0) red[warp][s] = v;
        }
        __syncthreads();
        if (tid < nc)
            out[sidx[tid]] = red[0][tid] + red[1][tid] + red[2][tid]
                           + red[3][tid] + b2;
        __syncthreads();   // protect xs/sidx/red before next chunk
    }
}

extern "C" void kernel_launch(void* const* d_in, const int* in_sizes, int n_in,
                              void* d_out, int out_size) {
    const float* x        = (const float*)d_in[0];
    const int*   task_ids = (const int*)  d_in[1];
    const float* l1_emb   = (const float*)d_in[2];
    const float* l1_bias  = (const float*)d_in[3];
    const float* l2_emb   = (const float*)d_in[4];
    const float* l2_bias  = (const float*)d_in[5];
    float* out = (float*)d_out;

    zero_kernel<<<(NTASK + 255) / 256, 256>>>();
    hist_kernel<<<(BATCH + 255) / 256, 256>>>(task_ids);
    scan_kernel<<<1, 1024>>>();
    scatter_kernel<<<(BATCH + 255) / 256, 256>>>(task_ids);
    task_mlp_grouped<<<NTASK, 128>>>(x, l1_emb, l1_bias, l2_emb, l2_bias, out);
}